// round 12
// baseline (speedup 1.0000x reference)
#include <cuda_runtime.h>

// VSampling: voxel-grid mean pooling, bitmask-compaction design v2.
//   inputs : coord [N,3] float32, offset [B] int32 (cumulative batch offsets)
//   outputs: n_p [N,3] f32, n_o [B], counts [N]  packed as float32
//
// ARITHMETIC: XLA rewrites x/0.05f -> x * 20.0f (f32(1/f32(0.05)) == 20.0f).
// grid = floor((c - min) * 20.0f) must use explicit rn mul/sub (no FMA).
//
// Rank structure: one 32B block per 128 keys: {uint bits[4]; int off; pad[3]}
// -> pass2 resolves a point's compacted rank with a single 32B L2 sector.

#define RINV 20.0f
#define MAXB 32
#define MAX_KEYS 25165824                 // capacity: G up to ~116
#define NBLK     (MAX_KEYS / 128)         // 196608 rank blocks (6.3 MB)
#define REDB     192                      // NBLK / 1024
#define N_MAX    4194304

__device__ uint4  g_blkv[NBLK * 2];       // [2i]=bits(16B), [2i+1].x=off
__device__ int    g_bsum[REDB];
__device__ int    g_bpre[REDB];
__device__ float4 g_vox[N_MAX];           // compacted {sx,sy,sz,cnt}
__device__ unsigned g_minbits[MAXB * 3];
__device__ unsigned g_maxbits[MAXB * 3];
__device__ int g_G, g_NKEY, g_nvox;
__device__ long long g_G3;

// ---------------------------------------------------------------- init
__global__ void k_init() {
    int t = threadIdx.x;
    if (t < MAXB * 3) { g_minbits[t] = 0x7f800000u; g_maxbits[t] = 0u; }
}

// ------------------------------------------------- per-batch min/max
__global__ void k_minmax(const float* __restrict__ coord,
                         const int* __restrict__ offset, int N, int B) {
    __shared__ unsigned smn[MAXB * 3], smx[MAXB * 3];
    __shared__ int soff[MAXB];
    for (int i = threadIdx.x; i < MAXB * 3; i += blockDim.x) {
        smn[i] = 0x7f800000u; smx[i] = 0u;
    }
    if (threadIdx.x < B) soff[threadIdx.x] = offset[threadIdx.x];
    __syncthreads();

    int per = (N + gridDim.x - 1) / gridDim.x;
    int s = blockIdx.x * per;
    int e = min(N, s + per);

    int curB = -1;
    unsigned mn0 = 0, mn1 = 0, mn2 = 0, mx0 = 0, mx1 = 0, mx2 = 0;
    for (int i = s + (int)threadIdx.x; i < e; i += blockDim.x) {
        int lo = 0, hi = B;
        while (lo < hi) { int mid = (lo + hi) >> 1; if (i < soff[mid]) hi = mid; else lo = mid + 1; }
        unsigned x = __float_as_uint(coord[3 * i + 0]);
        unsigned y = __float_as_uint(coord[3 * i + 1]);
        unsigned z = __float_as_uint(coord[3 * i + 2]);
        if (lo != curB) {
            if (curB >= 0) {
                atomicMin(&smn[curB * 3 + 0], mn0); atomicMax(&smx[curB * 3 + 0], mx0);
                atomicMin(&smn[curB * 3 + 1], mn1); atomicMax(&smx[curB * 3 + 1], mx1);
                atomicMin(&smn[curB * 3 + 2], mn2); atomicMax(&smx[curB * 3 + 2], mx2);
            }
            curB = lo;
            mn0 = mx0 = x; mn1 = mx1 = y; mn2 = mx2 = z;
        } else {
            mn0 = min(mn0, x); mx0 = max(mx0, x);
            mn1 = min(mn1, y); mx1 = max(mx1, y);
            mn2 = min(mn2, z); mx2 = max(mx2, z);
        }
    }
    if (curB >= 0) {
        atomicMin(&smn[curB * 3 + 0], mn0); atomicMax(&smx[curB * 3 + 0], mx0);
        atomicMin(&smn[curB * 3 + 1], mn1); atomicMax(&smx[curB * 3 + 1], mx1);
        atomicMin(&smn[curB * 3 + 2], mn2); atomicMax(&smx[curB * 3 + 2], mx2);
    }
    __syncthreads();
    for (int i = threadIdx.x; i < B * 3; i += blockDim.x) {
        if (smn[i] != 0x7f800000u) {
            atomicMin(&g_minbits[i], smn[i]);
            atomicMax(&g_maxbits[i], smx[i]);
        }
    }
}

// ------------------------------------------------- grid extent G
__global__ void k_computeG(int B) {
    __shared__ int sm[128];
    int t = threadIdx.x;
    int v = -1;
    if (t < B * 3 && g_minbits[t] != 0x7f800000u) {
        float mn = __uint_as_float(g_minbits[t]);
        float mx = __uint_as_float(g_maxbits[t]);
        v = (int)floorf(__fmul_rn(__fsub_rn(mx, mn), RINV));
    }
    sm[t] = v;
    __syncthreads();
    for (int o = 64; o > 0; o >>= 1) { if (t < o) sm[t] = max(sm[t], sm[t + o]); __syncthreads(); }
    if (t == 0) {
        int G = sm[0] + 1;
        if (G < 1) G = 1;
        long long G3 = (long long)G * G * G;
        long long nk = (long long)B * G3;
        if (nk > (long long)MAX_KEYS) nk = MAX_KEYS;
        g_G = G; g_G3 = G3;
        g_NKEY = (int)nk;
    }
}

// ------------------------------------------------- zero rank structure (6.3MB)
__global__ void k_zero_blk() {
    int stride = gridDim.x * blockDim.x;
    uint4 z = make_uint4(0u, 0u, 0u, 0u);
    for (int i = blockIdx.x * blockDim.x + threadIdx.x; i < NBLK * 2; i += stride)
        g_blkv[i] = z;
}

// ------------------------------------------------- pass1: mark occupancy
__global__ void k_pass1(const float* __restrict__ coord,
                        const int* __restrict__ offset, int N, int B) {
    __shared__ int soff[MAXB];
    __shared__ float sstart[MAXB * 3];
    __shared__ int sG;
    if (threadIdx.x < B) soff[threadIdx.x] = offset[threadIdx.x];
    if (threadIdx.x < B * 3) sstart[threadIdx.x] = __uint_as_float(g_minbits[threadIdx.x]);
    if (threadIdx.x == 0) sG = g_G;
    __syncthreads();
    int G = sG;
    unsigned* words = (unsigned*)g_blkv;
    int stride = gridDim.x * blockDim.x;
    for (int i = blockIdx.x * blockDim.x + threadIdx.x; i < N; i += stride) {
        int lo = 0, hi = B;
        while (lo < hi) { int mid = (lo + hi) >> 1; if (i < soff[mid]) hi = mid; else lo = mid + 1; }
        int b = lo;
        float x = coord[3 * i + 0];
        float y = coord[3 * i + 1];
        float z = coord[3 * i + 2];
        int gx = (int)floorf(__fmul_rn(__fsub_rn(x, sstart[b * 3 + 0]), RINV));
        int gy = (int)floorf(__fmul_rn(__fsub_rn(y, sstart[b * 3 + 1]), RINV));
        int gz = (int)floorf(__fmul_rn(__fsub_rn(z, sstart[b * 3 + 2]), RINV));
        int key = ((b * G + gx) * G + gy) * G + gz;
        if (key >= 0 && key < MAX_KEYS) {
            // word index inside 32B rank block: blk*8 + ((key>>5)&3)
            int w = ((key >> 7) << 3) + ((key >> 5) & 3);
            atomicOr(&words[w], 1u << (key & 31));
        }
    }
}

// ------------------------------------------------- scan level 1: block sums
// 192 blocks x 256 thr; thread handles 4 rank blocks (16 words).
__global__ void k_red() {
    int base = (blockIdx.x * 256 + threadIdx.x) * 4;
    int c = 0;
    #pragma unroll
    for (int j = 0; j < 4; j++) {
        uint4 bv = g_blkv[2 * (base + j)];
        c += __popc(bv.x) + __popc(bv.y) + __popc(bv.z) + __popc(bv.w);
    }
    // block reduce
    for (int o = 16; o > 0; o >>= 1) c += __shfl_down_sync(0xffffffffu, c, o);
    __shared__ int sred[8];
    if ((threadIdx.x & 31) == 0) sred[threadIdx.x >> 5] = c;
    __syncthreads();
    if (threadIdx.x == 0) {
        int t = 0;
        #pragma unroll
        for (int w = 0; w < 8; w++) t += sred[w];
        g_bsum[blockIdx.x] = t;
    }
}

// ------------------------------------------------- scan level 2: 192 partials
__global__ void k_scanmid() {
    __shared__ int sh[REDB];
    int t = threadIdx.x;
    int v = (t < REDB) ? g_bsum[t] : 0;
    if (t < REDB) sh[t] = v;
    __syncthreads();
    for (int o = 1; o < REDB; o <<= 1) {
        int add = (t < REDB && t >= o) ? sh[t - o] : 0;
        __syncthreads();
        if (t < REDB) sh[t] += add;
        __syncthreads();
    }
    if (t < REDB) g_bpre[t] = sh[t] - v;     // exclusive
    if (t == REDB - 1) g_nvox = sh[REDB - 1];
}

// ------------------------------------------------- scan level 3: fill offsets
__global__ void k_fill() {
    __shared__ int sh[256];
    int base = (blockIdx.x * 256 + threadIdx.x) * 4;
    int c[4];
    int tot = 0;
    #pragma unroll
    for (int j = 0; j < 4; j++) {
        uint4 bv = g_blkv[2 * (base + j)];
        c[j] = __popc(bv.x) + __popc(bv.y) + __popc(bv.z) + __popc(bv.w);
        tot += c[j];
    }
    sh[threadIdx.x] = tot;
    __syncthreads();
    for (int o = 1; o < 256; o <<= 1) {
        int add = (threadIdx.x >= (unsigned)o) ? sh[threadIdx.x - o] : 0;
        __syncthreads();
        sh[threadIdx.x] += add;
        __syncthreads();
    }
    int run = g_bpre[blockIdx.x] + sh[threadIdx.x] - tot;
    int* words = (int*)g_blkv;
    #pragma unroll
    for (int j = 0; j < 4; j++) {
        words[(base + j) * 8 + 4] = run;   // off field = second uint4 .x
        run += c[j];
    }
}

// ------------------------------------------------- zero compact scratch
__global__ void k_zero_vox() {
    int n = g_nvox;
    float4 z = make_float4(0.f, 0.f, 0.f, 0.f);
    int stride = gridDim.x * blockDim.x;
    for (int i = blockIdx.x * blockDim.x + threadIdx.x; i < n; i += stride)
        g_vox[i] = z;
}

// ------------------------------------------------- pass2: rank + accumulate
__global__ void k_pass2(const float* __restrict__ coord,
                        const int* __restrict__ offset, int N, int B) {
    __shared__ int soff[MAXB];
    __shared__ float sstart[MAXB * 3];
    __shared__ int sG;
    if (threadIdx.x < B) soff[threadIdx.x] = offset[threadIdx.x];
    if (threadIdx.x < B * 3) sstart[threadIdx.x] = __uint_as_float(g_minbits[threadIdx.x]);
    if (threadIdx.x == 0) sG = g_G;
    __syncthreads();
    int G = sG;
    int stride = gridDim.x * blockDim.x;
    for (int i = blockIdx.x * blockDim.x + threadIdx.x; i < N; i += stride) {
        int lo = 0, hi = B;
        while (lo < hi) { int mid = (lo + hi) >> 1; if (i < soff[mid]) hi = mid; else lo = mid + 1; }
        int b = lo;
        float x = coord[3 * i + 0];
        float y = coord[3 * i + 1];
        float z = coord[3 * i + 2];
        int gx = (int)floorf(__fmul_rn(__fsub_rn(x, sstart[b * 3 + 0]), RINV));
        int gy = (int)floorf(__fmul_rn(__fsub_rn(y, sstart[b * 3 + 1]), RINV));
        int gz = (int)floorf(__fmul_rn(__fsub_rn(z, sstart[b * 3 + 2]), RINV));
        int key = ((b * G + gx) * G + gy) * G + gz;
        if (key < 0 || key >= MAX_KEYS) continue;
        int blk = key >> 7;
        int wi  = (key >> 5) & 3;
        unsigned pmask = (1u << (key & 31)) - 1u;
        uint4 bv = g_blkv[2 * blk];          // same 32B sector as off
        int r = ((const int*)g_blkv)[blk * 8 + 4];
        unsigned m;
        m = (0 < wi) ? 0xffffffffu : ((0 == wi) ? pmask : 0u); r += __popc(bv.x & m);
        m = (1 < wi) ? 0xffffffffu : ((1 == wi) ? pmask : 0u); r += __popc(bv.y & m);
        m = (2 < wi) ? 0xffffffffu : ((2 == wi) ? pmask : 0u); r += __popc(bv.z & m);
        m = (3 == wi) ? pmask : 0u;                            r += __popc(bv.w & m);
        if (r >= 0 && r < N_MAX) {
            asm volatile("red.global.add.v4.f32 [%0], {%1, %2, %3, %4};"
                         :: "l"(&g_vox[r]), "f"(x), "f"(y), "f"(z), "f"(1.0f)
                         : "memory");
        }
    }
}

// ------------------------------------------------- finalize (means + tail + n_o)
__global__ void k_finalize(float* __restrict__ out, int N, int B, int full) {
    int nv = g_nvox;
    float* cntOut = out + (size_t)3 * N + B;
    int stride = gridDim.x * blockDim.x;
    for (int j = blockIdx.x * blockDim.x + threadIdx.x; j < N; j += stride) {
        if (j < nv) {
            float4 v = g_vox[j];
            float w = (v.w > 0.f) ? v.w : 1.f;
            out[3 * j + 0] = __fdiv_rn(v.x, w);
            out[3 * j + 1] = __fdiv_rn(v.y, w);
            out[3 * j + 2] = __fdiv_rn(v.z, w);
            if (full) cntOut[j] = v.w;
        } else {
            out[3 * j + 0] = 0.f;
            out[3 * j + 1] = 0.f;
            out[3 * j + 2] = 0.f;
            if (full) cntOut[j] = 0.f;
        }
    }
    // n_o: block 0, threads < B
    if (full && blockIdx.x == 0 && threadIdx.x < (unsigned)B) {
        int t = threadIdx.x;
        long long pos = (long long)(t + 1) * g_G3;
        if (pos > (long long)g_NKEY) pos = g_NKEY;
        int blk = (int)(pos >> 7);
        int c;
        if (blk >= NBLK) {
            c = g_nvox;
        } else {
            c = ((const int*)g_blkv)[blk * 8 + 4];
            uint4 bv = g_blkv[2 * blk];
            int fullw = (int)((pos >> 5) & 3);
            int rem   = (int)(pos & 31);
            unsigned wv[4] = {bv.x, bv.y, bv.z, bv.w};
            for (int w = 0; w < fullw; w++) c += __popc(wv[w]);
            if (rem) c += __popc(wv[fullw] & ((1u << rem) - 1u));
        }
        out[(size_t)3 * N + t] = (float)c;
    }
}

// ---------------------------------------------------------------- launch
extern "C" void kernel_launch(void* const* d_in, const int* in_sizes, int n_in,
                              void* d_out, int out_size) {
    const float* coord  = (const float*)d_in[0];
    const int*   offset = (const int*)d_in[1];
    int N = in_sizes[0] / 3;
    int B = in_sizes[1];
    float* out = (float*)d_out;
    int full = ((long long)out_size >= 4LL * N + B) ? 1 : 0;

    k_init<<<1, 128>>>();
    k_minmax<<<1184, 256>>>(coord, offset, N, B);
    k_computeG<<<1, 128>>>(B);
    k_zero_blk<<<592, 256>>>();
    k_pass1<<<2368, 256>>>(coord, offset, N, B);
    k_red<<<REDB, 256>>>();
    k_scanmid<<<1, 256>>>();
    k_zero_vox<<<2048, 256>>>();
    k_fill<<<REDB, 256>>>();
    k_pass2<<<2368, 256>>>(coord, offset, N, B);
    k_finalize<<<2048, 256>>>(out, N, B, full);
}

// round 13
// speedup vs baseline: 1.4700x; 1.4700x over previous
#include <cuda_runtime.h>

// VSampling: voxel-grid mean pooling, bitmask-compaction v3 (launch-fused).
//   inputs : coord [N,3] float32, offset [B] int32 (cumulative batch offsets)
//   outputs: n_p [N,3] f32, n_o [B], counts [N]  packed as float32
//
// ARITHMETIC: XLA rewrites x/0.05f -> x * 20.0f (f32(1/f32(0.05)) == 20.0f).
// grid = floor((c - min) * 20.0f) must use explicit rn mul/sub (no FMA).
//
// Rank structure: one 32B block per 128 keys: {uint bits[4]; int off; pad[3]}
// -> pass2 resolves a point's compacted rank with a single 32B L2 sector.

#define RINV 20.0f
#define MAXB 32
#define MAX_KEYS 25165824                 // capacity: G up to ~116
#define NBLK     (MAX_KEYS / 128)         // 196608 rank blocks (6.3 MB)
#define REDB     192                      // NBLK / 1024
#define N_MAX    4194304

__device__ uint4  g_blkv[NBLK * 2];       // [2i]=bits(16B), [2i+1].x=off
__device__ int    g_bsum[REDB];
__device__ int    g_bpre[REDB];
__device__ float4 g_vox[N_MAX];           // compacted {sx,sy,sz,cnt}
__device__ unsigned g_minbits[MAXB * 3];
__device__ unsigned g_maxbits[MAXB * 3];
__device__ int g_G, g_NKEY, g_nvox;
__device__ long long g_G3;

// ---------------------------------------------------------------- init
__global__ void k_init() {
    int t = threadIdx.x;
    if (t < MAXB * 3) { g_minbits[t] = 0x7f800000u; g_maxbits[t] = 0u; }
}

// ------------------------------------------------- per-batch min/max  (+ zero g_blkv)
__global__ void k_minmax(const float* __restrict__ coord,
                         const int* __restrict__ offset, int N, int B) {
    __shared__ unsigned smn[MAXB * 3], smx[MAXB * 3];
    __shared__ int soff[MAXB];
    for (int i = threadIdx.x; i < MAXB * 3; i += blockDim.x) {
        smn[i] = 0x7f800000u; smx[i] = 0u;
    }
    if (threadIdx.x < B) soff[threadIdx.x] = offset[threadIdx.x];
    __syncthreads();

    // fused: zero the rank structure (ordered before k_pass1 by kernel boundary)
    {
        uint4 z = make_uint4(0u, 0u, 0u, 0u);
        int stride = gridDim.x * blockDim.x;
        for (int i = blockIdx.x * blockDim.x + threadIdx.x; i < NBLK * 2; i += stride)
            g_blkv[i] = z;
    }

    int per = (N + gridDim.x - 1) / gridDim.x;
    int s = blockIdx.x * per;
    int e = min(N, s + per);

    int curB = -1;
    unsigned mn0 = 0, mn1 = 0, mn2 = 0, mx0 = 0, mx1 = 0, mx2 = 0;
    for (int i = s + (int)threadIdx.x; i < e; i += blockDim.x) {
        int lo = 0, hi = B;
        while (lo < hi) { int mid = (lo + hi) >> 1; if (i < soff[mid]) hi = mid; else lo = mid + 1; }
        unsigned x = __float_as_uint(coord[3 * i + 0]);
        unsigned y = __float_as_uint(coord[3 * i + 1]);
        unsigned z = __float_as_uint(coord[3 * i + 2]);
        if (lo != curB) {
            if (curB >= 0) {
                atomicMin(&smn[curB * 3 + 0], mn0); atomicMax(&smx[curB * 3 + 0], mx0);
                atomicMin(&smn[curB * 3 + 1], mn1); atomicMax(&smx[curB * 3 + 1], mx1);
                atomicMin(&smn[curB * 3 + 2], mn2); atomicMax(&smx[curB * 3 + 2], mx2);
            }
            curB = lo;
            mn0 = mx0 = x; mn1 = mx1 = y; mn2 = mx2 = z;
        } else {
            mn0 = min(mn0, x); mx0 = max(mx0, x);
            mn1 = min(mn1, y); mx1 = max(mx1, y);
            mn2 = min(mn2, z); mx2 = max(mx2, z);
        }
    }
    if (curB >= 0) {
        atomicMin(&smn[curB * 3 + 0], mn0); atomicMax(&smx[curB * 3 + 0], mx0);
        atomicMin(&smn[curB * 3 + 1], mn1); atomicMax(&smx[curB * 3 + 1], mx1);
        atomicMin(&smn[curB * 3 + 2], mn2); atomicMax(&smx[curB * 3 + 2], mx2);
    }
    __syncthreads();
    for (int i = threadIdx.x; i < B * 3; i += blockDim.x) {
        if (smn[i] != 0x7f800000u) {
            atomicMin(&g_minbits[i], smn[i]);
            atomicMax(&g_maxbits[i], smx[i]);
        }
    }
}

// ------------------------------------------------- grid extent G
__global__ void k_computeG(int B) {
    __shared__ int sm[128];
    int t = threadIdx.x;
    int v = -1;
    if (t < B * 3 && g_minbits[t] != 0x7f800000u) {
        float mn = __uint_as_float(g_minbits[t]);
        float mx = __uint_as_float(g_maxbits[t]);
        v = (int)floorf(__fmul_rn(__fsub_rn(mx, mn), RINV));
    }
    sm[t] = v;
    __syncthreads();
    for (int o = 64; o > 0; o >>= 1) { if (t < o) sm[t] = max(sm[t], sm[t + o]); __syncthreads(); }
    if (t == 0) {
        int G = sm[0] + 1;
        if (G < 1) G = 1;
        long long G3 = (long long)G * G * G;
        long long nk = (long long)B * G3;
        if (nk > (long long)MAX_KEYS) nk = MAX_KEYS;
        g_G = G; g_G3 = G3;
        g_NKEY = (int)nk;
    }
}

// ------------------------------------------------- pass1: mark occupancy (+ zero g_vox)
__global__ void k_pass1(const float* __restrict__ coord,
                        const int* __restrict__ offset, int N, int B) {
    __shared__ int soff[MAXB];
    __shared__ float sstart[MAXB * 3];
    __shared__ int sG;
    if (threadIdx.x < B) soff[threadIdx.x] = offset[threadIdx.x];
    if (threadIdx.x < B * 3) sstart[threadIdx.x] = __uint_as_float(g_minbits[threadIdx.x]);
    if (threadIdx.x == 0) sG = g_G;
    __syncthreads();
    int G = sG;
    unsigned* words = (unsigned*)g_blkv;
    int stride = gridDim.x * blockDim.x;
    int gid = blockIdx.x * blockDim.x + threadIdx.x;

    // fused: zero compacted scratch [0, N) — streaming stores overlap the
    // atomicOr latency below (nvox <= N always).
    {
        float4 z = make_float4(0.f, 0.f, 0.f, 0.f);
        for (int i = gid; i < N; i += stride)
            g_vox[i] = z;
    }

    for (int i = gid; i < N; i += stride) {
        int lo = 0, hi = B;
        while (lo < hi) { int mid = (lo + hi) >> 1; if (i < soff[mid]) hi = mid; else lo = mid + 1; }
        int b = lo;
        float x = coord[3 * i + 0];
        float y = coord[3 * i + 1];
        float z = coord[3 * i + 2];
        int gx = (int)floorf(__fmul_rn(__fsub_rn(x, sstart[b * 3 + 0]), RINV));
        int gy = (int)floorf(__fmul_rn(__fsub_rn(y, sstart[b * 3 + 1]), RINV));
        int gz = (int)floorf(__fmul_rn(__fsub_rn(z, sstart[b * 3 + 2]), RINV));
        int key = ((b * G + gx) * G + gy) * G + gz;
        if (key >= 0 && key < MAX_KEYS) {
            // word index inside 32B rank block: blk*8 + ((key>>5)&3)
            int w = ((key >> 7) << 3) + ((key >> 5) & 3);
            atomicOr(&words[w], 1u << (key & 31));
        }
    }
}

// ------------------------------------------------- scan level 1: block sums
__global__ void k_red() {
    int base = (blockIdx.x * 256 + threadIdx.x) * 4;
    int c = 0;
    #pragma unroll
    for (int j = 0; j < 4; j++) {
        uint4 bv = g_blkv[2 * (base + j)];
        c += __popc(bv.x) + __popc(bv.y) + __popc(bv.z) + __popc(bv.w);
    }
    for (int o = 16; o > 0; o >>= 1) c += __shfl_down_sync(0xffffffffu, c, o);
    __shared__ int sred[8];
    if ((threadIdx.x & 31) == 0) sred[threadIdx.x >> 5] = c;
    __syncthreads();
    if (threadIdx.x == 0) {
        int t = 0;
        #pragma unroll
        for (int w = 0; w < 8; w++) t += sred[w];
        g_bsum[blockIdx.x] = t;
    }
}

// ------------------------------------------------- scan level 2: 192 partials
__global__ void k_scanmid() {
    __shared__ int sh[REDB];
    int t = threadIdx.x;
    int v = (t < REDB) ? g_bsum[t] : 0;
    if (t < REDB) sh[t] = v;
    __syncthreads();
    for (int o = 1; o < REDB; o <<= 1) {
        int add = (t < REDB && t >= o) ? sh[t - o] : 0;
        __syncthreads();
        if (t < REDB) sh[t] += add;
        __syncthreads();
    }
    if (t < REDB) g_bpre[t] = sh[t] - v;     // exclusive
    if (t == REDB - 1) g_nvox = sh[REDB - 1];
}

// ------------------------------------------------- scan level 3: fill offsets
__global__ void k_fill() {
    __shared__ int sh[256];
    int base = (blockIdx.x * 256 + threadIdx.x) * 4;
    int c[4];
    int tot = 0;
    #pragma unroll
    for (int j = 0; j < 4; j++) {
        uint4 bv = g_blkv[2 * (base + j)];
        c[j] = __popc(bv.x) + __popc(bv.y) + __popc(bv.z) + __popc(bv.w);
        tot += c[j];
    }
    sh[threadIdx.x] = tot;
    __syncthreads();
    for (int o = 1; o < 256; o <<= 1) {
        int add = (threadIdx.x >= (unsigned)o) ? sh[threadIdx.x - o] : 0;
        __syncthreads();
        sh[threadIdx.x] += add;
        __syncthreads();
    }
    int run = g_bpre[blockIdx.x] + sh[threadIdx.x] - tot;
    int* words = (int*)g_blkv;
    #pragma unroll
    for (int j = 0; j < 4; j++) {
        words[(base + j) * 8 + 4] = run;   // off field = second uint4 .x
        run += c[j];
    }
}

// ------------------------------------------------- pass2: rank + accumulate
__global__ void k_pass2(const float* __restrict__ coord,
                        const int* __restrict__ offset, int N, int B) {
    __shared__ int soff[MAXB];
    __shared__ float sstart[MAXB * 3];
    __shared__ int sG;
    if (threadIdx.x < B) soff[threadIdx.x] = offset[threadIdx.x];
    if (threadIdx.x < B * 3) sstart[threadIdx.x] = __uint_as_float(g_minbits[threadIdx.x]);
    if (threadIdx.x == 0) sG = g_G;
    __syncthreads();
    int G = sG;
    int stride = gridDim.x * blockDim.x;
    for (int i = blockIdx.x * blockDim.x + threadIdx.x; i < N; i += stride) {
        int lo = 0, hi = B;
        while (lo < hi) { int mid = (lo + hi) >> 1; if (i < soff[mid]) hi = mid; else lo = mid + 1; }
        int b = lo;
        float x = coord[3 * i + 0];
        float y = coord[3 * i + 1];
        float z = coord[3 * i + 2];
        int gx = (int)floorf(__fmul_rn(__fsub_rn(x, sstart[b * 3 + 0]), RINV));
        int gy = (int)floorf(__fmul_rn(__fsub_rn(y, sstart[b * 3 + 1]), RINV));
        int gz = (int)floorf(__fmul_rn(__fsub_rn(z, sstart[b * 3 + 2]), RINV));
        int key = ((b * G + gx) * G + gy) * G + gz;
        if (key < 0 || key >= MAX_KEYS) continue;
        int blk = key >> 7;
        int wi  = (key >> 5) & 3;
        unsigned pmask = (1u << (key & 31)) - 1u;
        uint4 bv = g_blkv[2 * blk];          // same 32B sector as off
        int r = ((const int*)g_blkv)[blk * 8 + 4];
        unsigned m;
        m = (0 < wi) ? 0xffffffffu : ((0 == wi) ? pmask : 0u); r += __popc(bv.x & m);
        m = (1 < wi) ? 0xffffffffu : ((1 == wi) ? pmask : 0u); r += __popc(bv.y & m);
        m = (2 < wi) ? 0xffffffffu : ((2 == wi) ? pmask : 0u); r += __popc(bv.z & m);
        m = (3 == wi) ? pmask : 0u;                            r += __popc(bv.w & m);
        if (r >= 0 && r < N_MAX) {
            asm volatile("red.global.add.v4.f32 [%0], {%1, %2, %3, %4};"
                         :: "l"(&g_vox[r]), "f"(x), "f"(y), "f"(z), "f"(1.0f)
                         : "memory");
        }
    }
}

// ------------------------------------------------- finalize (means + tail + n_o)
__global__ void k_finalize(float* __restrict__ out, int N, int B, int full) {
    int nv = g_nvox;
    float* cntOut = out + (size_t)3 * N + B;
    int stride = gridDim.x * blockDim.x;
    for (int j = blockIdx.x * blockDim.x + threadIdx.x; j < N; j += stride) {
        if (j < nv) {
            float4 v = g_vox[j];
            float w = (v.w > 0.f) ? v.w : 1.f;
            out[3 * j + 0] = __fdiv_rn(v.x, w);
            out[3 * j + 1] = __fdiv_rn(v.y, w);
            out[3 * j + 2] = __fdiv_rn(v.z, w);
            if (full) cntOut[j] = v.w;
        } else {
            out[3 * j + 0] = 0.f;
            out[3 * j + 1] = 0.f;
            out[3 * j + 2] = 0.f;
            if (full) cntOut[j] = 0.f;
        }
    }
    // n_o: block 0, threads < B
    if (full && blockIdx.x == 0 && threadIdx.x < (unsigned)B) {
        int t = threadIdx.x;
        long long pos = (long long)(t + 1) * g_G3;
        if (pos > (long long)g_NKEY) pos = g_NKEY;
        int blk = (int)(pos >> 7);
        int c;
        if (blk >= NBLK) {
            c = g_nvox;
        } else {
            c = ((const int*)g_blkv)[blk * 8 + 4];
            uint4 bv = g_blkv[2 * blk];
            int fullw = (int)((pos >> 5) & 3);
            int rem   = (int)(pos & 31);
            unsigned wv[4] = {bv.x, bv.y, bv.z, bv.w};
            for (int w = 0; w < fullw; w++) c += __popc(wv[w]);
            if (rem) c += __popc(wv[fullw] & ((1u << rem) - 1u));
        }
        out[(size_t)3 * N + t] = (float)c;
    }
}

// ---------------------------------------------------------------- launch
extern "C" void kernel_launch(void* const* d_in, const int* in_sizes, int n_in,
                              void* d_out, int out_size) {
    const float* coord  = (const float*)d_in[0];
    const int*   offset = (const int*)d_in[1];
    int N = in_sizes[0] / 3;
    int B = in_sizes[1];
    float* out = (float*)d_out;
    int full = ((long long)out_size >= 4LL * N + B) ? 1 : 0;

    k_init<<<1, 128>>>();
    k_minmax<<<1184, 256>>>(coord, offset, N, B);
    k_computeG<<<1, 128>>>(B);
    k_pass1<<<2368, 256>>>(coord, offset, N, B);
    k_red<<<REDB, 256>>>();
    k_scanmid<<<1, 256>>>();
    k_fill<<<REDB, 256>>>();
    k_pass2<<<2368, 256>>>(coord, offset, N, B);
    k_finalize<<<2048, 256>>>(out, N, B, full);
}